// round 1
// baseline (speedup 1.0000x reference)
#include <cuda_runtime.h>
#include <math.h>

#define Bz 32
#define Sz 512
#define NB 20
#define EMB 128
#define INNER 128
#define VOCAB 40000
#define QL 20

typedef unsigned long long u64;

// ---- packed f32x2 helpers (FFMA2 path; ptxas never auto-emits this) ----
__device__ __forceinline__ u64 dup2(float a) {
    u64 r; asm("mov.b64 %0, {%1, %1};" : "=l"(r) : "f"(a)); return r;
}
__device__ __forceinline__ u64 pack2(float x, float y) {
    u64 r; asm("mov.b64 %0, {%1, %2};" : "=l"(r) : "f"(x), "f"(y)); return r;
}
__device__ __forceinline__ float2 unpack2(u64 v) {
    float2 f; asm("mov.b64 {%0, %1}, %2;" : "=f"(f.x), "=f"(f.y) : "l"(v)); return f;
}
__device__ __forceinline__ void ffma2(u64& d, u64 a, u64 b) {
    asm("fma.rn.f32x2 %0, %1, %2, %0;" : "+l"(d) : "l"(a), "l"(b));
}
__device__ __forceinline__ float neg_inf_f() { return __int_as_float(0xff800000); }

// ---- scratch (device globals; no allocation allowed) ----
__device__ float g_qc[Bz * INNER];
__device__ float g_tfv[Bz * INNER];
__device__ float g_uH[Bz * EMB];
__device__ float g_kb[NB * INNER];
__device__ u64   g_DE[EMB * INNER];          // interleaved (D[e][i], E[e][i])
__device__ float g_tm[Bz * Sz * EMB];        // temporal_memory, 8 MB
__device__ float g_talign[Bz * Sz];          // unmasked temporal align
__device__ float g_ob[Bz * EMB];             // o + u@H

// ============================================================
// prep: u[b] = sum_q emb[queries]*mult_mask ; qc = u@C ; tf = u@F ; uH = u@H
// grid Bz x 128
// ============================================================
__global__ void __launch_bounds__(128) k_prep(
    const int* __restrict__ queries, const float* __restrict__ emb,
    const float* __restrict__ mmask, const float* __restrict__ C,
    const float* __restrict__ F, const float* __restrict__ H)
{
    const int b = blockIdx.x, tid = threadIdx.x;
    __shared__ float su[EMB];
    float u = 0.f;
#pragma unroll
    for (int q = 0; q < QL; q++)
        u += emb[(size_t)queries[b * QL + q] * EMB + tid] * mmask[q * EMB + tid];
    su[tid] = u;
    __syncthreads();
    float c = 0.f, f = 0.f, h = 0.f;
#pragma unroll 4
    for (int e = 0; e < EMB; e++) {
        const float ue = su[e];
        c += ue * C[e * INNER + tid];
        f += ue * F[e * INNER + tid];
        h += ue * H[e * EMB + tid];
    }
    g_qc[b * INNER + tid]  = c;
    g_tfv[b * INNER + tid] = f;
    g_uH[b * EMB + tid]    = h;
}

// ============================================================
// kb[n] = emb[keys[n]] @ Bm       grid NB x 128
// ============================================================
__global__ void __launch_bounds__(128) k_kb(
    const int* __restrict__ keys, const float* __restrict__ emb,
    const float* __restrict__ Bm)
{
    const int n = blockIdx.x, tid = threadIdx.x;
    __shared__ float se[EMB];
    se[tid] = emb[(size_t)keys[n] * EMB + tid];
    __syncthreads();
    float a = 0.f;
#pragma unroll 4
    for (int e = 0; e < EMB; e++) a += se[e] * Bm[e * INNER + tid];
    g_kb[n * INNER + tid] = a;
}

// ============================================================
// interleave D,E into float2 pairs    grid 128 x 128
// ============================================================
__global__ void __launch_bounds__(128) k_de(const float* __restrict__ D,
                                            const float* __restrict__ E)
{
    const int i = blockIdx.x * 128 + threadIdx.x;
    g_DE[i] = pack2(D[i], E[i]);
}

// ============================================================
// main fused kernel: per (b,s) — ia GEMM (FFMA2), tanh, intratemporal
// softmax over NB, temporal_memory. grid (Sz, Bz) x 128
// ============================================================
__global__ void __launch_bounds__(128) k_main(
    const float* __restrict__ mem, const float* __restrict__ A,
    const float* __restrict__ v)
{
    const int s = blockIdx.x, b = blockIdx.y;
    const int tid = threadIdx.x, lane = tid & 31, wid = tid >> 5;

    __shared__ float smem_t[EMB * NB];   // [e][n], 80B per e-row (16B aligned)
    __shared__ float s_part[4 * NB];
    __shared__ float s_align[NB];

    // load memories tile transposed to [e][n]
    const float* mp = mem + ((size_t)(b * Sz + s)) * NB * EMB;
#pragma unroll
    for (int r = 0; r < NB; r++)
        smem_t[tid * NB + r] = mp[r * EMB + tid];
    __syncthreads();

    // ---- phase A: ia[n][i] for this thread's column i=tid, all n ----
    u64 acc[NB / 2];
#pragma unroll
    for (int j = 0; j < NB / 2; j++) acc[j] = 0ull;

#pragma unroll 4
    for (int e = 0; e < EMB; e++) {
        const u64 ad = dup2(A[e * INNER + tid]);
        const ulonglong2* row = (const ulonglong2*)(smem_t + e * NB);
#pragma unroll
        for (int k = 0; k < 5; k++) {
            const ulonglong2 m = row[k];
            ffma2(acc[2 * k],     ad, m.x);
            ffma2(acc[2 * k + 1], ad, m.y);
        }
    }

    // ---- tanh + v-weighted, reduce over i for each n ----
    const float qci = g_qc[b * INNER + tid];
    const float vi  = v[tid];
    float tv[NB];
#pragma unroll
    for (int j = 0; j < NB / 2; j++) {
        const float2 f = unpack2(acc[j]);
        tv[2 * j]     = vi * tanhf(f.x + g_kb[(2 * j) * INNER + tid] + qci);
        tv[2 * j + 1] = vi * tanhf(f.y + g_kb[(2 * j + 1) * INNER + tid] + qci);
    }
#pragma unroll
    for (int n = 0; n < NB; n++) {
        float t = tv[n];
#pragma unroll
        for (int o = 16; o > 0; o >>= 1) t += __shfl_xor_sync(0xffffffffu, t, o);
        tv[n] = t;
    }
    if (lane == 0) {
#pragma unroll
        for (int n = 0; n < NB; n++) s_part[wid * NB + n] = tv[n];
    }
    __syncthreads();
    if (tid < NB)
        s_align[tid] = s_part[tid] + s_part[NB + tid] + s_part[2 * NB + tid] + s_part[3 * NB + tid];
    __syncthreads();

    // ---- softmax over NB (redundant per-thread, NB=20) ----
    float p[NB];
    float mx = -1e30f;
#pragma unroll
    for (int n = 0; n < NB; n++) { p[n] = s_align[n]; mx = fmaxf(mx, p[n]); }
    float Z = 0.f;
#pragma unroll
    for (int n = 0; n < NB; n++) { p[n] = expf(p[n] - mx); Z += p[n]; }
    const float invZ = 1.f / Z;

    // ---- temporal_memory[e=tid] ----
    float tm = 0.f;
    const float4* r4 = (const float4*)(smem_t + tid * NB);
#pragma unroll
    for (int k = 0; k < 5; k++) {
        const float4 m4 = r4[k];
        tm += p[4 * k] * m4.x + p[4 * k + 1] * m4.y + p[4 * k + 2] * m4.z + p[4 * k + 3] * m4.w;
    }
    tm *= invZ;
    g_tm[((size_t)(b * Sz + s)) * EMB + tid] = tm;
}

// ============================================================
// temporal alignment: talign[b,s] = sum_i w[i]*tanh(tm@D + story@E + tf)
// 16 sentences per CTA to amortize D/E traffic. grid (Sz/16, Bz) x 128
// ============================================================
#define ST 16
__global__ void __launch_bounds__(128) k_align2(
    const float* __restrict__ stories, const float* __restrict__ w)
{
    const int b = blockIdx.y, s0 = blockIdx.x * ST;
    const int tid = threadIdx.x, lane = tid & 31, wid = tid >> 5;

    __shared__ u64 sp[EMB * ST];       // [e][si] = (tm, story)
    __shared__ float s_part[4 * ST];

#pragma unroll
    for (int si = 0; si < ST; si++) {
        const size_t base = ((size_t)(b * Sz + s0 + si)) * EMB + tid;
        sp[tid * ST + si] = pack2(g_tm[base], stories[base]);
    }
    __syncthreads();

    u64 acc[ST];
#pragma unroll
    for (int si = 0; si < ST; si++) acc[si] = 0ull;

#pragma unroll 2
    for (int e = 0; e < EMB; e++) {
        const u64 de = g_DE[e * INNER + tid];
        const ulonglong2* row = (const ulonglong2*)(sp + e * ST);
#pragma unroll
        for (int k = 0; k < ST / 2; k++) {
            const ulonglong2 m = row[k];
            ffma2(acc[2 * k],     m.x, de);
            ffma2(acc[2 * k + 1], m.y, de);
        }
    }

    const float tfi = g_tfv[b * INNER + tid];
    const float wi  = w[tid];
    float tv[ST];
#pragma unroll
    for (int si = 0; si < ST; si++) {
        const float2 f = unpack2(acc[si]);
        float t = wi * tanhf(f.x + f.y + tfi);
#pragma unroll
        for (int o = 16; o > 0; o >>= 1) t += __shfl_xor_sync(0xffffffffu, t, o);
        tv[si] = t;
    }
    if (lane == 0) {
#pragma unroll
        for (int si = 0; si < ST; si++) s_part[wid * ST + si] = tv[si];
    }
    __syncthreads();
    if (tid < ST)
        g_talign[b * Sz + s0 + tid] =
            s_part[tid] + s_part[ST + tid] + s_part[2 * ST + tid] + s_part[3 * ST + tid];
}

// ============================================================
// temporal softmax over S + readout o ; ob = o + u@H. grid Bz x 128
// ============================================================
__global__ void __launch_bounds__(128) k_temporal(const float* __restrict__ mask)
{
    const int b = blockIdx.x, tid = threadIdx.x, lane = tid & 31, wid = tid >> 5;
    __shared__ float sp[Sz];
    __shared__ float sr[4];

    float vals[4];
    float mx = neg_inf_f();
#pragma unroll
    for (int r = 0; r < 4; r++) {
        const int s = r * 128 + tid;
        const float ta = g_talign[b * Sz + s];
        const float m  = mask[b * Sz + s];
        const float ml = (m != 0.f) ? ta * m : neg_inf_f();
        vals[r] = ml;
        mx = fmaxf(mx, ml);
    }
#pragma unroll
    for (int o = 16; o > 0; o >>= 1) mx = fmaxf(mx, __shfl_xor_sync(0xffffffffu, mx, o));
    if (lane == 0) sr[wid] = mx;
    __syncthreads();
    mx = fmaxf(fmaxf(sr[0], sr[1]), fmaxf(sr[2], sr[3]));
    __syncthreads();

    float Z = 0.f;
#pragma unroll
    for (int r = 0; r < 4; r++) {
        const float ev = expf(vals[r] - mx);
        sp[r * 128 + tid] = ev;
        Z += ev;
    }
#pragma unroll
    for (int o = 16; o > 0; o >>= 1) Z += __shfl_xor_sync(0xffffffffu, Z, o);
    if (lane == 0) sr[wid] = Z;
    __syncthreads();
    Z = sr[0] + sr[1] + sr[2] + sr[3];
    const float invZ = 1.f / Z;

    float o_ = 0.f;
    const float* tmb = g_tm + (size_t)b * Sz * EMB + tid;
#pragma unroll 8
    for (int s = 0; s < Sz; s++) o_ += sp[s] * tmb[(size_t)s * EMB];
    g_ob[b * EMB + tid] = o_ * invZ + g_uH[b * EMB + tid];
}

// ============================================================
// logits = ob @ R, b packed in pairs via FFMA2. grid ceil(VOCAB/128) x 128
// ============================================================
__global__ void __launch_bounds__(128) k_logits(const float* __restrict__ R,
                                                float* __restrict__ out)
{
    __shared__ u64 so2[EMB * (Bz / 2)];   // [e][bpair]
    const int tid = threadIdx.x;
#pragma unroll
    for (int r = 0; r < EMB * (Bz / 2) / 128; r++) {
        const int idx = r * 128 + tid;
        const int e = idx >> 4, bb = idx & 15;
        so2[idx] = pack2(g_ob[(2 * bb) * EMB + e], g_ob[(2 * bb + 1) * EMB + e]);
    }
    __syncthreads();

    const int col = blockIdx.x * 128 + tid;
    if (col >= VOCAB) return;

    u64 acc[Bz / 2];
#pragma unroll
    for (int j = 0; j < Bz / 2; j++) acc[j] = 0ull;

#pragma unroll 2
    for (int e = 0; e < EMB; e++) {
        const u64 rd = dup2(R[(size_t)e * VOCAB + col]);
        const u64* row = so2 + e * (Bz / 2);
#pragma unroll
        for (int bb = 0; bb < Bz / 2; bb++) ffma2(acc[bb], rd, row[bb]);
    }
#pragma unroll
    for (int bb = 0; bb < Bz / 2; bb++) {
        const float2 f = unpack2(acc[bb]);
        out[(size_t)(2 * bb) * VOCAB + col]     = f.x;
        out[(size_t)(2 * bb + 1) * VOCAB + col] = f.y;
    }
}

// ============================================================
extern "C" void kernel_launch(void* const* d_in, const int* in_sizes, int n_in,
                              void* d_out, int out_size)
{
    const float* memories = (const float*)d_in[0];
    const float* stories  = (const float*)d_in[1];
    const float* smask    = (const float*)d_in[2];
    const int*   queries  = (const int*)  d_in[3];
    const int*   keys     = (const int*)  d_in[4];
    const float* emb      = (const float*)d_in[5];
    const float* mmask    = (const float*)d_in[6];
    const float* A        = (const float*)d_in[7];
    const float* Bm       = (const float*)d_in[8];
    const float* C        = (const float*)d_in[9];
    const float* v        = (const float*)d_in[10];
    const float* D        = (const float*)d_in[11];
    const float* E        = (const float*)d_in[12];
    const float* F        = (const float*)d_in[13];
    const float* w        = (const float*)d_in[14];
    const float* H        = (const float*)d_in[15];
    const float* R        = (const float*)d_in[16];
    float* out = (float*)d_out;

    k_prep<<<Bz, 128>>>(queries, emb, mmask, C, F, H);
    k_kb<<<NB, 128>>>(keys, emb, Bm);
    k_de<<<EMB * INNER / 128, 128>>>(D, E);
    k_main<<<dim3(Sz, Bz), 128>>>(memories, A, v);
    k_align2<<<dim3(Sz / ST, Bz), 128>>>(stories, w);
    k_temporal<<<Bz, 128>>>(smask);
    k_logits<<<(VOCAB + 127) / 128, 128>>>(R, out);
}